// round 13
// baseline (speedup 1.0000x reference)
#include <cuda_runtime.h>
#include <math.h>

typedef unsigned long long u64;

// ---------------- shapes ----------------
#define BERT 768
#define CTRY 24
#define CODE 8
#define GAZ  9
#define MIX  24
#define NFEAT 13
#define CMAX 64
#define B_MAX 2048
#define NCTRY_MAX 512
#define NCODES_MAX 1024

// ---------------- device scratch ----------------
__device__ float g_cet [NCTRY_MAX * CTRY];   // projected country embeddings (raw)
__device__ float g_cetn[NCTRY_MAX];          // their norms
__device__ float g_coden[NCODES_MAX];        // code-embedding norms
__device__ float g_proj[B_MAX * 80];         // x(24)|x_code(8)|x_other(24)|x_doc(24)

// ---------------- f32x2 helpers ----------------
__device__ __forceinline__ void ffma2(u64& d, u64 a, u64 b) {
    asm("fma.rn.f32x2 %0, %1, %2, %0;" : "+l"(d) : "l"(a), "l"(b));
}
__device__ __forceinline__ u64 pack2(float lo, float hi) {
    u64 r; asm("mov.b64 %0, {%1,%2};" : "=l"(r) : "f"(lo), "f"(hi)); return r;
}
__device__ __forceinline__ void unpack2(u64 v, float& lo, float& hi) {
    asm("mov.b64 {%0,%1}, %2;" : "=f"(lo), "=f"(hi) : "l"(v));
}
__device__ __forceinline__ float hsum2(u64 v) {
    float lo, hi; unpack2(v, lo, hi); return lo + hi;
}
__device__ __forceinline__ float sigf(float x) {
    float t; asm("tanh.approx.f32 %0, %1;" : "=f"(t) : "f"(x * 0.5f));
    return fmaf(0.5f, t, 0.5f);
}
__device__ __forceinline__ void pf_l2(const void* p) {
    asm volatile("prefetch.global.L2 [%0];" :: "l"(p));
}

#define PF_BLOCKS 16

// =====================================================================
// k_pre @ 512 threads.  Grid: [0,PF) L2-prefetch | [PF,PF+PB) proj |
// [..,+CB) cet (4 countries via 4x128 groups) | rest: code norms.
//
// proj: 512 thr = 8 row-pairs x 64 k-slices(12 floats). 16 rows/block,
// 10 passes, double-buffered smem weights. Same tile shape & total
// LDS/FFMA2 work as the 256-thr version but 16 warps/SM instead of 8.
// =====================================================================
__global__ void __launch_bounds__(512, 1) k_pre(
    const float* __restrict__ place, const float* __restrict__ other,
    const float* __restrict__ doc,
    const float* __restrict__ Wt2c, const float* __restrict__ bt2c,
    const float* __restrict__ Wcode, const float* __restrict__ bcode,
    const float* __restrict__ Wctx, const float* __restrict__ bctx,
    const float* __restrict__ cemb, const float* __restrict__ Wcet,
    const float* __restrict__ bcet, const float* __restrict__ codeTab,
    const int* __restrict__ fcodes, const int* __restrict__ ccodes,
    const float* __restrict__ gaz,
    int PB, int CB, int nCtry, int nCodes, int Bn)
{
    __shared__ __align__(16) float sW[2][8 * BERT];   // 2 x 24KB weight tiles
    __shared__ __align__(16) float sred[16 * 136];    // 16 warps x 128 (padded)
    const int bid  = blockIdx.x;
    const int tid  = threadIdx.x;
    const int warp = tid >> 5, lane = tid & 31;

    if (bid < PF_BLOCKS) {
        // ---- L2 prefetch of k_mlp's streaming inputs ----
        const int PFT = PF_BLOCKS * 512;
        int t = bid * 512 + tid;
        int gl = (Bn * CMAX * GAZ * 4 + 127) >> 7;
        for (int j = t; j < gl; j += PFT)
            pf_l2((const char*)gaz + ((size_t)j << 7));
        int cl = (Bn * CMAX * 4 + 127) >> 7;
        for (int j = t; j < cl; j += PFT) {
            pf_l2((const char*)fcodes + ((size_t)j << 7));
            pf_l2((const char*)ccodes + ((size_t)j << 7));
        }
        return;
    }

    if (bid < PF_BLOCKS + PB) {
        // ---------------- projections ----------------
        const int rg   = lane & 7;                    // row-pair 0..7 (16 rows)
        const int ksl  = (warp << 2) | (lane >> 3);   // k-slice 0..63
        const int koff = ksl * 12;
        const int row0 = (bid - PF_BLOCKS) * 16;
        const int rA = min(row0 + rg * 2,     Bn - 1);
        const int rB = min(row0 + rg * 2 + 1, Bn - 1);

        u64 xA[6], xB[6];
        float4 wst[3];

        {   // stage pass-0 weights (Wt2c rows 0..7): 1536 float4, 3/thread
            const float4* src = (const float4*)Wt2c;
            #pragma unroll
            for (int j = 0; j < 3; j++) wst[j] = __ldg(src + tid + j * 512);
            float4* dst = (float4*)sW[0];
            #pragma unroll
            for (int j = 0; j < 3; j++) dst[tid + j * 512] = wst[j];
        }
        __syncthreads();

        int cur = 0;
        #pragma unroll 1
        for (int bb = 0; bb < 10; bb++) {
            if (bb < 9) {   // prefetch next weight tile into regs
                int nb = bb + 1;
                const float* Wn = (nb < 3)  ? Wt2c + nb * 8 * BERT
                                : (nb == 3) ? Wcode
                                : (nb < 7)  ? Wctx + (nb - 4) * 8 * BERT
                                :             Wctx + (nb - 7) * 8 * BERT;
                const float4* src = (const float4*)Wn;
                #pragma unroll
                for (int j = 0; j < 3; j++) wst[j] = __ldg(src + tid + j * 512);
            }
            if (bb == 0 || bb == 4 || bb == 7) {   // source switch
                const float* srcp = (bb == 0) ? place : (bb == 4) ? other : doc;
                const ulonglong2* pa = (const ulonglong2*)(srcp + (size_t)rA * BERT + koff);
                const ulonglong2* pb = (const ulonglong2*)(srcp + (size_t)rB * BERT + koff);
                #pragma unroll
                for (int j = 0; j < 3; j++) {
                    ulonglong2 va = __ldg(pa + j); xA[2*j] = va.x; xA[2*j+1] = va.y;
                    ulonglong2 vb = __ldg(pb + j); xB[2*j] = vb.x; xB[2*j+1] = vb.y;
                }
            }
            const float* Wsm = sW[cur];
            float rA8[8], rB8[8];
            #pragma unroll
            for (int ob = 0; ob < 8; ob++) {
                const ulonglong2* w = (const ulonglong2*)(Wsm + ob * BERT + koff);
                u64 sA = 0ull, sB = 0ull;
                #pragma unroll
                for (int j = 0; j < 3; j++) {
                    ulonglong2 wv = w[j];
                    ffma2(sA, xA[2*j], wv.x); ffma2(sA, xA[2*j+1], wv.y);
                    ffma2(sB, xB[2*j], wv.x); ffma2(sB, xB[2*j+1], wv.y);
                }
                float a = hsum2(sA), b = hsum2(sB);
                a += __shfl_xor_sync(0xffffffffu, a, 8);
                a += __shfl_xor_sync(0xffffffffu, a, 16);
                b += __shfl_xor_sync(0xffffffffu, b, 8);
                b += __shfl_xor_sync(0xffffffffu, b, 16);
                rA8[ob] = a; rB8[ob] = b;
            }
            if (lane < 8) {
                float* p = sred + warp * 136 + lane * 16;
                #pragma unroll
                for (int ob = 0; ob < 8; ob++) { p[ob] = rA8[ob]; p[8 + ob] = rB8[ob]; }
            }
            __syncthreads();
            if (bb < 9) {
                float4* dst = (float4*)sW[cur ^ 1];
                #pragma unroll
                for (int j = 0; j < 3; j++) dst[tid + j * 512] = wst[j];
            }
            if (tid < 128) {
                int rr = tid >> 3, ob = tid & 7;     // row 0..15, out 0..7
                int pair = rr >> 1, ab = rr & 1;
                float a = 0.f;
                #pragma unroll
                for (int w2 = 0; w2 < 16; w2++)
                    a += sred[w2 * 136 + pair * 16 + ab * 8 + ob];
                if (row0 + rr < Bn) {
                    int seg; float bias;
                    if      (bb < 3)  { seg = bb * 8;             bias = bt2c[bb * 8 + ob]; }
                    else if (bb == 3) { seg = 24;                 bias = bcode[ob]; }
                    else if (bb < 7)  { seg = 32 + (bb - 4) * 8;  bias = bctx[(bb - 4) * 8 + ob]; }
                    else              { seg = 56 + (bb - 7) * 8;  bias = bctx[(bb - 7) * 8 + ob]; }
                    g_proj[(row0 + rr) * 80 + seg + ob] = a + bias;
                }
            }
            __syncthreads();
            cur ^= 1;
        }
    } else if (bid < PF_BLOCKS + PB + CB) {
        // ---------- cet projection + norm: 4 countries in parallel ----------
        const int grp = tid >> 7;                 // 0..3
        const int wg  = (warp & 3);               // warp within group
        const int wt  = tid & 127;
        const int i = (bid - PF_BLOCKS - PB) * 4 + grp;
        float* sv = sred + grp * 32;
        if (i < nCtry) {
            const float* e = cemb + (size_t)i * BERT;
            #pragma unroll
            for (int t = 0; t < 6; t++) {
                int j = wg * 6 + t;
                const float* w = Wcet + (size_t)j * BERT;
                float a = 0.f;
                #pragma unroll
                for (int q = 0; q < 6; q++) {
                    int k = lane * 4 + q * 128;
                    float4 ev = __ldg((const float4*)(e + k));
                    float4 wv = __ldg((const float4*)(w + k));
                    a += ev.x * wv.x + ev.y * wv.y + ev.z * wv.z + ev.w * wv.w;
                }
                #pragma unroll
                for (int o = 16; o; o >>= 1) a += __shfl_xor_sync(0xffffffffu, a, o);
                if (lane == 0) sv[j] = a + bcet[j];
            }
        }
        __syncthreads();
        if (i < nCtry && wt < 32) {
            float v = (lane < CTRY) ? sv[lane] : 0.f;
            if (lane < CTRY) g_cet[i * CTRY + lane] = v;
            float s = v * v;
            #pragma unroll
            for (int o = 16; o; o >>= 1) s += __shfl_xor_sync(0xffffffffu, s, o);
            if (lane == 0) g_cetn[i] = sqrtf(s);
        }
    } else {
        // ---------- code-embedding norms ----------
        int i = (bid - PF_BLOCKS - PB - CB) * 512 + tid;
        if (i < nCodes) {
            float s = 0.f;
            #pragma unroll
            for (int j = 0; j < CODE; j++) { float v = codeTab[i * CODE + j]; s += v * v; }
            g_coden[i] = sqrtf(s);
        }
    }
}

// =====================================================================
// k_mlp — VERBATIM the R7-measured 19.07us version.
// 128 thr = 4 rows x 32 lanes; each lane does candidates c, c+32.
// =====================================================================
__global__ void __launch_bounds__(128, 5) k_mlp(
    const int* __restrict__ fcodes, const int* __restrict__ ccodes,
    const float* __restrict__ gaz,  const float* __restrict__ codeTab,
    const float* __restrict__ W1, const float* __restrict__ b1,
    const float* __restrict__ W2, const float* __restrict__ b2,
    const float* __restrict__ WL, const float* __restrict__ bL,
    float* __restrict__ out, int Bn)
{
    __shared__ __align__(16) float sW1T[NFEAT * MIX];   // [q][j]
    __shared__ __align__(16) float sW2[MIX * MIX];      // [j][q]
    __shared__ __align__(16) float sB1[MIX];
    __shared__ float sB2[MIX], sWL[MIX];
    __shared__ __align__(16) float sGaz[4 * CMAX * GAZ];
    __shared__ __align__(16) float sX[4 * 80];
    __shared__ float sN[4][4];
    __shared__ float sbL;

    const int tid = threadIdx.x;
    const int b0  = blockIdx.x * 4;

    for (int i = tid; i < NFEAT * MIX; i += 128) {
        int q = i / MIX, j = i - q * MIX;
        sW1T[i] = W1[j * NFEAT + q];
    }
    for (int i = tid; i < MIX * MIX; i += 128) sW2[i] = W2[i];
    if (tid < MIX) { sB1[tid] = b1[tid]; sB2[tid] = b2[tid]; sWL[tid] = WL[tid]; }
    if (tid == 0) sbL = bL[0];
    {
        int cnt = min(576, (Bn - b0) * 144);
        const float4* gp = (const float4*)gaz + (size_t)b0 * 144;
        float4* sp = (float4*)sGaz;
        for (int i = tid; i < cnt; i += 128) sp[i] = __ldg(gp + i);
    }
    for (int i = tid; i < 4 * 80; i += 128) {
        int bb = min(b0 + i / 80, Bn - 1);
        sX[i] = g_proj[bb * 80 + (i % 80)];
    }
    __syncthreads();

    if (tid < 16) {
        int gg = tid >> 2, which = tid & 3;
        int off = (which == 0) ? 0 : (which == 1) ? 24 : (which == 2) ? 32 : 56;
        int cnt = (which == 1) ? CODE : CTRY;
        float ss = 0.f;
        for (int j = 0; j < cnt; j++) { float v = sX[gg * 80 + off + j]; ss += v * v; }
        sN[gg][which] = fmaxf(sqrtf(ss), 1e-8f);
    }
    __syncthreads();

    const int g    = tid >> 5;
    const int lane = tid & 31;
    const int b    = min(b0 + g, Bn - 1);
    const int idx0 = b * CMAX + lane;
    const int idx1 = idx0 + 32;
    const int fc0 = fcodes[idx0], cc0 = ccodes[idx0];
    const int fc1 = fcodes[idx1], cc1 = ccodes[idx1];
    const float* sx = sX + g * 80;

    const ulonglong2* cet0 = (const ulonglong2*)(g_cet + cc0 * CTRY);
    const ulonglong2* cet1 = (const ulonglong2*)(g_cet + cc1 * CTRY);
    const u64* x1 = (const u64*)(sx);
    const u64* x3 = (const u64*)(sx + 32);
    const u64* x4 = (const u64*)(sx + 56);
    u64 p10=0, p30=0, p40=0, p11=0, p31=0, p41=0;
    #pragma unroll
    for (int j = 0; j < 6; j++) {
        ulonglong2 c0 = __ldg(cet0 + j);
        ulonglong2 c1 = __ldg(cet1 + j);
        u64 xa = x1[2*j], xb = x1[2*j+1];
        ffma2(p10, xa, c0.x); ffma2(p10, xb, c0.y);
        ffma2(p11, xa, c1.x); ffma2(p11, xb, c1.y);
        xa = x3[2*j]; xb = x3[2*j+1];
        ffma2(p30, xa, c0.x); ffma2(p30, xb, c0.y);
        ffma2(p31, xa, c1.x); ffma2(p31, xb, c1.y);
        xa = x4[2*j]; xb = x4[2*j+1];
        ffma2(p40, xa, c0.x); ffma2(p40, xb, c0.y);
        ffma2(p41, xa, c1.x); ffma2(p41, xb, c1.y);
    }
    const ulonglong2* fe0 = (const ulonglong2*)(codeTab + fc0 * CODE);
    const ulonglong2* fe1 = (const ulonglong2*)(codeTab + fc1 * CODE);
    const u64* x2p = (const u64*)(sx + 24);
    u64 p20 = 0, p21 = 0;
    #pragma unroll
    for (int j = 0; j < 2; j++) {
        ulonglong2 c0 = __ldg(fe0 + j);
        ulonglong2 c1 = __ldg(fe1 + j);
        u64 xa = x2p[2*j], xb = x2p[2*j+1];
        ffma2(p20, xa, c0.x); ffma2(p20, xb, c0.y);
        ffma2(p21, xa, c1.x); ffma2(p21, xb, c1.y);
    }
    float nb0 = fmaxf(g_cetn[cc0], 1e-8f);
    float nb1 = fmaxf(g_cetn[cc1], 1e-8f);
    float feat0[4], feat1[4];
    feat0[0] = __fdividef(hsum2(p10), sN[g][0] * nb0);
    feat0[1] = __fdividef(hsum2(p20), sN[g][1] * fmaxf(g_coden[fc0], 1e-8f));
    feat0[2] = __fdividef(hsum2(p30), sN[g][2] * nb0);
    feat0[3] = __fdividef(hsum2(p40), sN[g][3] * nb0);
    feat1[0] = __fdividef(hsum2(p11), sN[g][0] * nb1);
    feat1[1] = __fdividef(hsum2(p21), sN[g][1] * fmaxf(g_coden[fc1], 1e-8f));
    feat1[2] = __fdividef(hsum2(p31), sN[g][2] * nb1);
    feat1[3] = __fdividef(hsum2(p41), sN[g][3] * nb1);

    u64 a0[12], a1[12];
    const u64* b1p = (const u64*)sB1;
    #pragma unroll
    for (int j = 0; j < 12; j++) { a0[j] = b1p[j]; a1[j] = b1p[j]; }

    const float* gz0 = sGaz + ((g * CMAX) + lane) * GAZ;
    const float* gz1 = gz0 + 32 * GAZ;
    #pragma unroll
    for (int q = 0; q < NFEAT; q++) {
        float f0 = (q < 4) ? feat0[q] : gz0[q - 4];
        float f1 = (q < 4) ? feat1[q] : gz1[q - 4];
        u64 ff0 = pack2(f0, f0), ff1 = pack2(f1, f1);
        const ulonglong2* wc = (const ulonglong2*)(sW1T + q * MIX);
        #pragma unroll
        for (int j2 = 0; j2 < 6; j2++) {
            ulonglong2 wv = wc[j2];
            ffma2(a0[2*j2],   ff0, wv.x); ffma2(a0[2*j2+1], ff0, wv.y);
            ffma2(a1[2*j2],   ff1, wv.x); ffma2(a1[2*j2+1], ff1, wv.y);
        }
    }
    #pragma unroll
    for (int j = 0; j < 12; j++) {
        float lo, hi;
        unpack2(a0[j], lo, hi); a0[j] = pack2(sigf(lo), sigf(hi));
        unpack2(a1[j], lo, hi); a1[j] = pack2(sigf(lo), sigf(hi));
    }

    float last0 = sbL, last1 = sbL;
    #pragma unroll
    for (int j = 0; j < MIX; j++) {
        const ulonglong2* wr = (const ulonglong2*)(sW2 + j * MIX);
        u64 s0 = 0ull, s1 = 0ull;
        #pragma unroll
        for (int q2 = 0; q2 < 6; q2++) {
            ulonglong2 wv = wr[q2];
            ffma2(s0, a0[2*q2],   wv.x); ffma2(s0, a0[2*q2+1], wv.y);
            ffma2(s1, a1[2*q2],   wv.x); ffma2(s1, a1[2*q2+1], wv.y);
        }
        float v0 = sB2[j] + hsum2(s0);
        float v1 = sB2[j] + hsum2(s1);
        last0 = fmaf(sWL[j], sigf(v0), last0);
        last1 = fmaf(sWL[j], sigf(v1), last1);
    }

    float m = fmaxf(last0, last1);
    #pragma unroll
    for (int o = 16; o; o >>= 1) m = fmaxf(m, __shfl_xor_sync(0xffffffffu, m, o));
    float e0 = __expf(last0 - m);
    float e1 = __expf(last1 - m);
    float ss = e0 + e1;
    #pragma unroll
    for (int o = 16; o; o >>= 1) ss += __shfl_xor_sync(0xffffffffu, ss, o);
    float inv = __fdividef(1.f, ss);
    if (b0 + g < Bn) {
        out[idx0] = e0 * inv;
        out[idx1] = e1 * inv;
    }
}

// =====================================================================
extern "C" void kernel_launch(void* const* d_in, const int* in_sizes, int n_in,
                              void* d_out, int out_size)
{
    const float* place  = (const float*)d_in[0];
    const float* other  = (const float*)d_in[1];
    const float* doc    = (const float*)d_in[2];
    const int*   fcodes = (const int*)  d_in[3];
    const int*   ccodes = (const int*)  d_in[4];
    const float* gaz    = (const float*)d_in[5];
    const float* codeTab= (const float*)d_in[6];
    const float* ctryTab= (const float*)d_in[7];
    const float* Wcet   = (const float*)d_in[8];
    const float* bcet   = (const float*)d_in[9];
    const float* Wt2c   = (const float*)d_in[10];
    const float* bt2c   = (const float*)d_in[11];
    const float* Wctx   = (const float*)d_in[12];
    const float* bctx   = (const float*)d_in[13];
    const float* Wcode  = (const float*)d_in[14];
    const float* bcode  = (const float*)d_in[15];
    const float* W1     = (const float*)d_in[16];
    const float* b1     = (const float*)d_in[17];
    const float* W2     = (const float*)d_in[18];
    const float* b2     = (const float*)d_in[19];
    const float* WL     = (const float*)d_in[20];
    const float* bL     = (const float*)d_in[21];
    float* out = (float*)d_out;

    int B      = in_sizes[0] / BERT;
    int nCtry  = in_sizes[7] / BERT;
    int nCodes = in_sizes[6] / CODE;

    int PB = (B + 15) / 16;
    int CB = (nCtry + 3) / 4;
    int grid = PF_BLOCKS + PB + CB + (nCodes + 511) / 512;

    k_pre<<<grid, 512>>>(place, other, doc,
                         Wt2c, bt2c, Wcode, bcode, Wctx, bctx,
                         ctryTab, Wcet, bcet, codeTab,
                         fcodes, ccodes, gaz,
                         PB, CB, nCtry, nCodes, B);
    k_mlp<<<(B + 3) / 4, 128>>>(fcodes, ccodes, gaz, codeTab,
                                W1, b1, W2, b2, WL, bL, out, B);
}

// round 14
// speedup vs baseline: 1.4367x; 1.4367x over previous
#include <cuda_runtime.h>
#include <math.h>

typedef unsigned long long u64;

// ---------------- shapes ----------------
#define BERT 768
#define CTRY 24
#define CODE 8
#define GAZ  9
#define MIX  24
#define NFEAT 13
#define CMAX 64
#define B_MAX 2048
#define NCTRY_MAX 512
#define NCODES_MAX 1024

// ---------------- device scratch ----------------
__device__ float g_cet  [NCTRY_MAX * CTRY];   // NORMALIZED projected country embs
__device__ float g_codeN[NCODES_MAX * CODE];  // NORMALIZED code embeddings
__device__ float g_proj [B_MAX * 80];         // x(24)|x_code(8)|x_other(24)|x_doc(24)
__device__ int   g_flag [256];                // per-proj-block done flags
__device__ int   g_aux;                       // cet+codeN done counter

// ---------------- f32x2 helpers ----------------
__device__ __forceinline__ void ffma2(u64& d, u64 a, u64 b) {
    asm("fma.rn.f32x2 %0, %1, %2, %0;" : "+l"(d) : "l"(a), "l"(b));
}
__device__ __forceinline__ u64 pack2(float lo, float hi) {
    u64 r; asm("mov.b64 %0, {%1,%2};" : "=l"(r) : "f"(lo), "f"(hi)); return r;
}
__device__ __forceinline__ void unpack2(u64 v, float& lo, float& hi) {
    asm("mov.b64 {%0,%1}, %2;" : "=f"(lo), "=f"(hi) : "l"(v));
}
__device__ __forceinline__ float hsum2(u64 v) {
    float lo, hi; unpack2(v, lo, hi); return lo + hi;
}
__device__ __forceinline__ float sigf(float x) {
    float t; asm("tanh.approx.f32 %0, %1;" : "=f"(t) : "f"(x * 0.5f));
    return fmaf(0.5f, t, 0.5f);
}
__device__ __forceinline__ void pf_l2(const void* p) {
    asm volatile("prefetch.global.L2 [%0];" :: "l"(p));
}

#define PF_BLOCKS 16
#define SMEM_FLOATS 13360   // 53.4KB carved per-section

__global__ void k_reset() {
    if (threadIdx.x < 256) g_flag[threadIdx.x] = 0;
    if (threadIdx.x == 0)  g_aux = 0;
}

// =====================================================================
// Fused kernel. Grid order (deadlock-safe: producers strictly before
// consumers): [0,PF) prefetch | [PF,+PB) proj(8 rows, flags) |
// [+,+CB) cet | [+,+CN) codeN | [+,+PB) mlp (waits on flags)
// =====================================================================
__global__ void __launch_bounds__(256, 2) k_main(
    const float* __restrict__ place, const float* __restrict__ other,
    const float* __restrict__ doc,
    const float* __restrict__ Wt2c, const float* __restrict__ bt2c,
    const float* __restrict__ Wcode, const float* __restrict__ bcode,
    const float* __restrict__ Wctx, const float* __restrict__ bctx,
    const float* __restrict__ cemb, const float* __restrict__ Wcet,
    const float* __restrict__ bcet, const float* __restrict__ codeTab,
    const int* __restrict__ fcodes, const int* __restrict__ ccodes,
    const float* __restrict__ gaz,
    const float* __restrict__ W1, const float* __restrict__ b1,
    const float* __restrict__ W2, const float* __restrict__ b2,
    const float* __restrict__ WL, const float* __restrict__ bL,
    float* __restrict__ out,
    int PB, int CB, int CN, int nCtry, int nCodes, int Bn)
{
    __shared__ __align__(16) float smem[SMEM_FLOATS];
    const int bid  = blockIdx.x;
    const int tid  = threadIdx.x;
    const int warp = tid >> 5, lane = tid & 31;

    if (bid < PF_BLOCKS) {
        // ---------------- L2 prefetch of mlp inputs ----------------
        const int PFT = PF_BLOCKS * 256;
        int t = bid * 256 + tid;
        int gl = (Bn * CMAX * GAZ * 4 + 127) >> 7;
        for (int j = t; j < gl; j += PFT)
            pf_l2((const char*)gaz + ((size_t)j << 7));
        int cl = (Bn * CMAX * 4 + 127) >> 7;
        for (int j = t; j < cl; j += PFT) {
            pf_l2((const char*)fcodes + ((size_t)j << 7));
            pf_l2((const char*)ccodes + ((size_t)j << 7));
        }
        return;
    }

    if (bid < PF_BLOCKS + PB) {
        // ================= proj: 8 rows, ctx-share, dbl-buffered W ====
        float* sW0  = smem;
        float* sW1s = smem + 6144;
        float* sred = smem + 12288;          // 1064 floats used
        const int grp  = bid - PF_BLOCKS;
        const int rg   = lane & 3;
        const int ksl  = (warp << 3) | (lane >> 2);
        const int koff = ksl * 12;
        const int row0 = grp * 8;
        const int rA = min(row0 + rg * 2,     Bn - 1);
        const int rB = min(row0 + rg * 2 + 1, Bn - 1);

        u64 xPA[6], xPB[6], xOA[6], xOB[6], xDA[6], xDB[6];
        #define LDX(dst, src, r) { \
            const ulonglong2* p_ = (const ulonglong2*)((src) + (size_t)(r) * BERT + koff); \
            ulonglong2 v0 = __ldg(p_), v1 = __ldg(p_ + 1), v2 = __ldg(p_ + 2);            \
            dst[0]=v0.x; dst[1]=v0.y; dst[2]=v1.x; dst[3]=v1.y; dst[4]=v2.x; dst[5]=v2.y; }
        LDX(xPA, place, rA); LDX(xPB, place, rB);
        LDX(xOA, other, rA); LDX(xOB, other, rB);
        LDX(xDA, doc,   rA); LDX(xDB, doc,   rB);
        #undef LDX

        float4 wst[6];
        {
            const float4* src = (const float4*)Wt2c;
            #pragma unroll
            for (int j = 0; j < 6; j++) wst[j] = __ldg(src + tid + j * 256);
            float4* dst = (float4*)sW0;
            #pragma unroll
            for (int j = 0; j < 6; j++) dst[tid + j * 256] = wst[j];
        }
        __syncthreads();

        int cur = 0;
        #pragma unroll 1
        for (int bb = 0; bb < 7; bb++) {
            if (bb < 6) {
                int nb = bb + 1;
                const float* Wn = (nb < 3)  ? Wt2c + nb * 8 * BERT
                                : (nb == 3) ? Wcode
                                :             Wctx + (nb - 4) * 8 * BERT;
                const float4* src = (const float4*)Wn;
                #pragma unroll
                for (int j = 0; j < 6; j++) wst[j] = __ldg(src + tid + j * 256);
            }
            const float* Wsm = cur ? sW1s : sW0;

            if (bb < 4) {
                float rA8[8], rB8[8];
                #pragma unroll
                for (int ob = 0; ob < 8; ob++) {
                    const ulonglong2* w = (const ulonglong2*)(Wsm + ob * BERT + koff);
                    u64 sA = 0ull, sB = 0ull;
                    #pragma unroll
                    for (int j = 0; j < 3; j++) {
                        ulonglong2 wv = w[j];
                        ffma2(sA, xPA[2*j], wv.x); ffma2(sA, xPA[2*j+1], wv.y);
                        ffma2(sB, xPB[2*j], wv.x); ffma2(sB, xPB[2*j+1], wv.y);
                    }
                    float a = hsum2(sA), b = hsum2(sB);
                    a += __shfl_xor_sync(0xffffffffu, a, 4);
                    a += __shfl_xor_sync(0xffffffffu, a, 8);
                    a += __shfl_xor_sync(0xffffffffu, a, 16);
                    b += __shfl_xor_sync(0xffffffffu, b, 4);
                    b += __shfl_xor_sync(0xffffffffu, b, 8);
                    b += __shfl_xor_sync(0xffffffffu, b, 16);
                    rA8[ob] = a; rB8[ob] = b;
                }
                if (lane < 4) {
                    float* p = sred + warp * 132 + rg * 16;
                    #pragma unroll
                    for (int ob = 0; ob < 8; ob++) { p[ob] = rA8[ob]; p[8 + ob] = rB8[ob]; }
                }
                __syncthreads();
                if (bb < 6) {
                    float4* dst = (float4*)(cur ? sW0 : sW1s);
                    #pragma unroll
                    for (int j = 0; j < 6; j++) dst[tid + j * 256] = wst[j];
                }
                if (tid < 64) {
                    int rr = tid >> 3, ob = tid & 7;
                    float a = 0.f;
                    #pragma unroll
                    for (int w2 = 0; w2 < 8; w2++)
                        a += sred[w2 * 132 + (rr >> 1) * 16 + (rr & 1) * 8 + ob];
                    if (row0 + rr < Bn) {
                        int seg = (bb < 3) ? bb * 8 : 24;
                        float bias = (bb < 3) ? bt2c[bb * 8 + ob] : bcode[ob];
                        g_proj[(row0 + rr) * 80 + seg + ob] = a + bias;
                    }
                }
            } else {
                float oA8[8], oB8[8], dA8[8], dB8[8];
                #pragma unroll
                for (int ob = 0; ob < 8; ob++) {
                    const ulonglong2* w = (const ulonglong2*)(Wsm + ob * BERT + koff);
                    u64 so = 0ull, sp = 0ull, sq = 0ull, sr = 0ull;
                    #pragma unroll
                    for (int j = 0; j < 3; j++) {
                        ulonglong2 wv = w[j];
                        ffma2(so, xOA[2*j], wv.x); ffma2(so, xOA[2*j+1], wv.y);
                        ffma2(sp, xOB[2*j], wv.x); ffma2(sp, xOB[2*j+1], wv.y);
                        ffma2(sq, xDA[2*j], wv.x); ffma2(sq, xDA[2*j+1], wv.y);
                        ffma2(sr, xDB[2*j], wv.x); ffma2(sr, xDB[2*j+1], wv.y);
                    }
                    float a = hsum2(so), b = hsum2(sp), c = hsum2(sq), d = hsum2(sr);
                    #pragma unroll
                    for (int o = 4; o <= 16; o <<= 1) {
                        a += __shfl_xor_sync(0xffffffffu, a, o);
                        b += __shfl_xor_sync(0xffffffffu, b, o);
                        c += __shfl_xor_sync(0xffffffffu, c, o);
                        d += __shfl_xor_sync(0xffffffffu, d, o);
                    }
                    oA8[ob] = a; oB8[ob] = b; dA8[ob] = c; dB8[ob] = d;
                }
                if (lane < 4) {
                    float* p = sred + warp * 132 + rg * 32;
                    #pragma unroll
                    for (int ob = 0; ob < 8; ob++) {
                        p[ob] = oA8[ob]; p[8 + ob] = oB8[ob];
                        p[16 + ob] = dA8[ob]; p[24 + ob] = dB8[ob];
                    }
                }
                __syncthreads();
                if (bb < 6) {
                    float4* dst = (float4*)(cur ? sW0 : sW1s);
                    #pragma unroll
                    for (int j = 0; j < 6; j++) dst[tid + j * 256] = wst[j];
                }
                if (tid < 128) {
                    int od = tid >> 6;
                    int rr = (tid >> 3) & 7;
                    int ob = tid & 7;
                    float a = 0.f;
                    #pragma unroll
                    for (int w2 = 0; w2 < 8; w2++)
                        a += sred[w2 * 132 + (rr >> 1) * 32 + od * 16 + (rr & 1) * 8 + ob];
                    if (row0 + rr < Bn) {
                        int wr0 = (bb - 4) * 8;
                        g_proj[(row0 + rr) * 80 + 32 + od * 24 + wr0 + ob] = a + bctx[wr0 + ob];
                    }
                }
            }
            __syncthreads();
            cur ^= 1;
        }
        // publish this block's 8 rows
        __threadfence();
        __syncthreads();
        if (tid == 0) *(volatile int*)&g_flag[grp] = 1;
        return;
    }

    if (bid < PF_BLOCKS + PB + CB) {
        // ================= cet projection + NORMALIZE ================
        float* sv = smem;
        const int i0 = (bid - PF_BLOCKS - PB) * 4;
        #pragma unroll 1
        for (int t4 = 0; t4 < 4; t4++) {
            int i = i0 + t4;
            if (i < nCtry) {
                const float* e = cemb + (size_t)i * BERT;
                #pragma unroll
                for (int t = 0; t < 3; t++) {
                    int j = warp * 3 + t;
                    const float* w = Wcet + (size_t)j * BERT;
                    float a = 0.f;
                    #pragma unroll
                    for (int q = 0; q < 6; q++) {
                        int k = lane * 4 + q * 128;
                        float4 ev = *(const float4*)(e + k);
                        float4 wv = __ldg((const float4*)(w + k));
                        a += ev.x * wv.x + ev.y * wv.y + ev.z * wv.z + ev.w * wv.w;
                    }
                    #pragma unroll
                    for (int o = 16; o; o >>= 1) a += __shfl_xor_sync(0xffffffffu, a, o);
                    if (lane == 0) sv[j] = a + bcet[j];
                }
            }
            __syncthreads();
            if (i < nCtry && tid < 32) {
                float v = (lane < CTRY) ? sv[lane] : 0.f;
                float s = v * v;
                #pragma unroll
                for (int o = 16; o; o >>= 1) s += __shfl_xor_sync(0xffffffffu, s, o);
                float rinv = __fdividef(1.f, fmaxf(sqrtf(s), 1e-8f));
                if (lane < CTRY) g_cet[i * CTRY + lane] = v * rinv;
            }
            __syncthreads();
        }
        __threadfence();
        __syncthreads();
        if (tid == 0) atomicAdd(&g_aux, 1);
        return;
    }

    if (bid < PF_BLOCKS + PB + CB + CN) {
        // ================= normalized code embeddings ================
        int i = (bid - PF_BLOCKS - PB - CB) * 256 + tid;
        if (i < nCodes) {
            float s = 0.f;
            float v[CODE];
            #pragma unroll
            for (int j = 0; j < CODE; j++) { v[j] = codeTab[i * CODE + j]; s += v[j] * v[j]; }
            float rinv = __fdividef(1.f, fmaxf(sqrtf(s), 1e-8f));
            #pragma unroll
            for (int j = 0; j < CODE; j++) g_codeN[i * CODE + j] = v[j] * rinv;
        }
        __threadfence();
        __syncthreads();
        if (tid == 0) atomicAdd(&g_aux, 1);
        return;
    }

    // ================= MLP: 8 rows x 32 lanes, 2 cands/thread ========
    {
        const int mb = bid - (PF_BLOCKS + PB + CB + CN);
        const int b0 = mb * 8;

        // wait for this block's proj rows + the small tables
        if (tid == 0) {
            while (*(volatile int*)&g_flag[mb] == 0) __nanosleep(100);
            while (*(volatile int*)&g_aux < CB + CN) __nanosleep(100);
        }
        __syncthreads();
        __threadfence();

        float* sW1T = smem;             // 312 (pad to 320)
        float* sW2  = smem + 320;       // 576
        float* sB1  = smem + 896;       // 24
        float* sB2  = smem + 920;       // 24
        float* sWL  = smem + 944;       // 24
        float* sbLp = smem + 968;       // 1
        float* sNi  = smem + 976;       // 32
        float* sX   = smem + 1024;      // 640
        float* sGaz = smem + 1664;      // 4608

        for (int i = tid; i < NFEAT * MIX; i += 256) {
            int q = i / MIX, j = i - q * MIX;
            sW1T[i] = W1[j * NFEAT + q];
        }
        for (int i = tid; i < MIX * MIX; i += 256) sW2[i] = W2[i];
        if (tid < MIX) { sB1[tid] = b1[tid]; sB2[tid] = b2[tid]; sWL[tid] = WL[tid]; }
        if (tid == 0) sbLp[0] = bL[0];
        {
            int cnt = min(1152, (Bn - b0) * 144);
            const float4* gp = (const float4*)gaz + (size_t)b0 * 144;
            float4* sp = (float4*)sGaz;
            for (int i = tid; i < cnt; i += 256) sp[i] = __ldg(gp + i);
        }
        for (int i = tid; i < 8 * 80; i += 256) {
            int bb = min(b0 + i / 80, Bn - 1);
            sX[i] = g_proj[bb * 80 + (i % 80)];
        }
        __syncthreads();

        if (tid < 32) {
            int gg = tid >> 2, which = tid & 3;
            int off = (which == 0) ? 0 : (which == 1) ? 24 : (which == 2) ? 32 : 56;
            int cnt = (which == 1) ? CODE : CTRY;
            float ss = 0.f;
            for (int j = 0; j < cnt; j++) { float v = sX[gg * 80 + off + j]; ss += v * v; }
            sNi[gg * 4 + which] = __fdividef(1.f, fmaxf(sqrtf(ss), 1e-8f));
        }
        __syncthreads();
        for (int i = tid; i < 8 * 80; i += 256) {
            int r = i / 80, o = i - r * 80;
            int seg = (o < 24) ? 0 : (o < 32) ? 1 : (o < 56) ? 2 : 3;
            sX[i] *= sNi[r * 4 + seg];
        }
        __syncthreads();

        const int g = warp;               // row 0..7
        const int b = min(b0 + g, Bn - 1);
        const int idx0 = b * CMAX + lane;
        const int idx1 = idx0 + 32;
        const int fc0 = fcodes[idx0], cc0 = ccodes[idx0];
        const int fc1 = fcodes[idx1], cc1 = ccodes[idx1];
        const float* sx = sX + g * 80;

        const ulonglong2* cet0 = (const ulonglong2*)(g_cet + cc0 * CTRY);
        const ulonglong2* cet1 = (const ulonglong2*)(g_cet + cc1 * CTRY);
        const u64* x1 = (const u64*)(sx);
        const u64* x3 = (const u64*)(sx + 32);
        const u64* x4 = (const u64*)(sx + 56);
        u64 p10=0, p30=0, p40=0, p11=0, p31=0, p41=0;
        #pragma unroll
        for (int j = 0; j < 6; j++) {
            ulonglong2 c0 = __ldg(cet0 + j);
            ulonglong2 c1 = __ldg(cet1 + j);
            u64 xa = x1[2*j], xb = x1[2*j+1];
            ffma2(p10, xa, c0.x); ffma2(p10, xb, c0.y);
            ffma2(p11, xa, c1.x); ffma2(p11, xb, c1.y);
            xa = x3[2*j]; xb = x3[2*j+1];
            ffma2(p30, xa, c0.x); ffma2(p30, xb, c0.y);
            ffma2(p31, xa, c1.x); ffma2(p31, xb, c1.y);
            xa = x4[2*j]; xb = x4[2*j+1];
            ffma2(p40, xa, c0.x); ffma2(p40, xb, c0.y);
            ffma2(p41, xa, c1.x); ffma2(p41, xb, c1.y);
        }
        const ulonglong2* fe0 = (const ulonglong2*)(g_codeN + fc0 * CODE);
        const ulonglong2* fe1 = (const ulonglong2*)(g_codeN + fc1 * CODE);
        const u64* x2p = (const u64*)(sx + 24);
        u64 p20 = 0, p21 = 0;
        #pragma unroll
        for (int j = 0; j < 2; j++) {
            ulonglong2 c0 = __ldg(fe0 + j);
            ulonglong2 c1 = __ldg(fe1 + j);
            u64 xa = x2p[2*j], xb = x2p[2*j+1];
            ffma2(p20, xa, c0.x); ffma2(p20, xb, c0.y);
            ffma2(p21, xa, c1.x); ffma2(p21, xb, c1.y);
        }
        float feat0[4], feat1[4];
        feat0[0] = hsum2(p10); feat0[1] = hsum2(p20);
        feat0[2] = hsum2(p30); feat0[3] = hsum2(p40);
        feat1[0] = hsum2(p11); feat1[1] = hsum2(p21);
        feat1[2] = hsum2(p31); feat1[3] = hsum2(p41);

        u64 a0[12], a1[12];
        const u64* b1p = (const u64*)sB1;
        #pragma unroll
        for (int j = 0; j < 12; j++) { a0[j] = b1p[j]; a1[j] = b1p[j]; }

        const float* gz0 = sGaz + ((g * CMAX) + lane) * GAZ;
        const float* gz1 = gz0 + 32 * GAZ;
        #pragma unroll
        for (int q = 0; q < NFEAT; q++) {
            float f0 = (q < 4) ? feat0[q] : gz0[q - 4];
            float f1 = (q < 4) ? feat1[q] : gz1[q - 4];
            u64 ff0 = pack2(f0, f0), ff1 = pack2(f1, f1);
            const ulonglong2* wc = (const ulonglong2*)(sW1T + q * MIX);
            #pragma unroll
            for (int j2 = 0; j2 < 6; j2++) {
                ulonglong2 wv = wc[j2];
                ffma2(a0[2*j2],   ff0, wv.x); ffma2(a0[2*j2+1], ff0, wv.y);
                ffma2(a1[2*j2],   ff1, wv.x); ffma2(a1[2*j2+1], ff1, wv.y);
            }
        }
        #pragma unroll
        for (int j = 0; j < 12; j++) {
            float lo, hi;
            unpack2(a0[j], lo, hi); a0[j] = pack2(sigf(lo), sigf(hi));
            unpack2(a1[j], lo, hi); a1[j] = pack2(sigf(lo), sigf(hi));
        }

        float last0 = sbLp[0], last1 = sbLp[0];
        #pragma unroll
        for (int j = 0; j < MIX; j++) {
            const ulonglong2* wr = (const ulonglong2*)(sW2 + j * MIX);
            u64 s0 = 0ull, s1 = 0ull;
            #pragma unroll
            for (int q2 = 0; q2 < 6; q2++) {
                ulonglong2 wv = wr[q2];
                ffma2(s0, a0[2*q2],   wv.x); ffma2(s0, a0[2*q2+1], wv.y);
                ffma2(s1, a1[2*q2],   wv.x); ffma2(s1, a1[2*q2+1], wv.y);
            }
            float v0 = sB2[j] + hsum2(s0);
            float v1 = sB2[j] + hsum2(s1);
            last0 = fmaf(sWL[j], sigf(v0), last0);
            last1 = fmaf(sWL[j], sigf(v1), last1);
        }

        float m = fmaxf(last0, last1);
        #pragma unroll
        for (int o = 16; o; o >>= 1) m = fmaxf(m, __shfl_xor_sync(0xffffffffu, m, o));
        float e0 = __expf(last0 - m);
        float e1 = __expf(last1 - m);
        float ss = e0 + e1;
        #pragma unroll
        for (int o = 16; o; o >>= 1) ss += __shfl_xor_sync(0xffffffffu, ss, o);
        float inv = __fdividef(1.f, ss);
        if (b0 + g < Bn) {
            out[idx0] = e0 * inv;
            out[idx1] = e1 * inv;
        }
    }
}

// =====================================================================
extern "C" void kernel_launch(void* const* d_in, const int* in_sizes, int n_in,
                              void* d_out, int out_size)
{
    const float* place  = (const float*)d_in[0];
    const float* other  = (const float*)d_in[1];
    const float* doc    = (const float*)d_in[2];
    const int*   fcodes = (const int*)  d_in[3];
    const int*   ccodes = (const int*)  d_in[4];
    const float* gaz    = (const float*)d_in[5];
    const float* codeTab= (const float*)d_in[6];
    const float* ctryTab= (const float*)d_in[7];
    const float* Wcet   = (const float*)d_in[8];
    const float* bcet   = (const float*)d_in[9];
    const float* Wt2c   = (const float*)d_in[10];
    const float* bt2c   = (const float*)d_in[11];
    const float* Wctx   = (const float*)d_in[12];
    const float* bctx   = (const float*)d_in[13];
    const float* Wcode  = (const float*)d_in[14];
    const float* bcode  = (const float*)d_in[15];
    const float* W1     = (const float*)d_in[16];
    const float* b1     = (const float*)d_in[17];
    const float* W2     = (const float*)d_in[18];
    const float* b2     = (const float*)d_in[19];
    const float* WL     = (const float*)d_in[20];
    const float* bL     = (const float*)d_in[21];
    float* out = (float*)d_out;

    int B      = in_sizes[0] / BERT;
    int nCtry  = in_sizes[7] / BERT;
    int nCodes = in_sizes[6] / CODE;

    int PB = (B + 7) / 8;                 // proj AND mlp block count (1:1 flags)
    int CB = (nCtry + 3) / 4;
    int CN = (nCodes + 255) / 256;
    int grid = PF_BLOCKS + PB + CB + CN + PB;

    k_reset<<<1, 256>>>();
    k_main<<<grid, 256>>>(place, other, doc,
                          Wt2c, bt2c, Wcode, bcode, Wctx, bctx,
                          ctryTab, Wcet, bcet, codeTab,
                          fcodes, ccodes, gaz,
                          W1, b1, W2, b2, WL, bL, out,
                          PB, CB, CN, nCtry, nCodes, B);
}

// round 15
// speedup vs baseline: 1.5109x; 1.0517x over previous
#include <cuda_runtime.h>
#include <math.h>

typedef unsigned long long u64;

// ---------------- shapes ----------------
#define BERT 768
#define CTRY 24
#define CODE 8
#define GAZ  9
#define MIX  24
#define NFEAT 13
#define CMAX 64
#define B_MAX 2048
#define NCTRY_MAX 512
#define NCODES_MAX 1024

// ---------------- device scratch ----------------
__device__ float g_cet [NCTRY_MAX * CTRY];   // projected country embeddings (raw)
__device__ float g_cetn[NCTRY_MAX];          // their norms
__device__ float g_coden[NCODES_MAX];        // code-embedding norms
__device__ float g_proj[B_MAX * 80];         // x(24)|x_code(8)|x_other(24)|x_doc(24)

// ---------------- helpers ----------------
__device__ __forceinline__ void ffma2(u64& d, u64 a, u64 b) {
    asm("fma.rn.f32x2 %0, %1, %2, %0;" : "+l"(d) : "l"(a), "l"(b));
}
__device__ __forceinline__ u64 pack2(float lo, float hi) {
    u64 r; asm("mov.b64 %0, {%1,%2};" : "=l"(r) : "f"(lo), "f"(hi)); return r;
}
__device__ __forceinline__ void unpack2(u64 v, float& lo, float& hi) {
    asm("mov.b64 {%0,%1}, %2;" : "=f"(lo), "=f"(hi) : "l"(v));
}
__device__ __forceinline__ float hsum2(u64 v) {
    float lo, hi; unpack2(v, lo, hi); return lo + hi;
}
__device__ __forceinline__ float sigf(float x) {
    float t; asm("tanh.approx.f32 %0, %1;" : "=f"(t) : "f"(x * 0.5f));
    return fmaf(0.5f, t, 0.5f);
}
__device__ __forceinline__ void pf_l2(const void* p) {
    asm volatile("prefetch.global.L2 [%0];" :: "l"(p));
}
__device__ __forceinline__ float to_tf32(float x) {
    float y; asm("cvt.rna.tf32.f32 %0, %1;" : "=f"(y) : "f"(x)); return y;
}
__device__ __forceinline__ void mma_tf32(float* c,
    float a0, float a1, float a2, float a3, float b0, float b1)
{
    asm volatile(
        "mma.sync.aligned.m16n8k8.row.col.f32.tf32.tf32.f32 "
        "{%0,%1,%2,%3}, {%4,%5,%6,%7}, {%8,%9}, {%0,%1,%2,%3};"
        : "+f"(c[0]), "+f"(c[1]), "+f"(c[2]), "+f"(c[3])
        : "r"(__float_as_uint(a0)), "r"(__float_as_uint(a1)),
          "r"(__float_as_uint(a2)), "r"(__float_as_uint(a3)),
          "r"(__float_as_uint(b0)), "r"(__float_as_uint(b1)));
}

// ---------------- MMA proj kernel geometry ----------------
#define KC 96            // k-chunk
#define NCHUNK 8         // 768 / 96
#define SA_STR 100       // 96 + 4 pad -> bank = (4*row + col) % 32, conflict-free
#define SB_STR 100
#define PF_BLK 8

// =====================================================================
// k_mma: grid = [0,3nb) proj jobs | [3nb,+cb) cet job | [+cnb) code norms
//        | [+PF_BLK) L2 prefetch.   128 threads/block.
// Each job block: M=64 rows x N<=32 outs, K=768 via TF32 mma.sync.
// Warp w owns m16 tile w; fragments per PTX m16n8k8 tf32 layout.
// =====================================================================
__global__ void __launch_bounds__(128) k_mma(
    const float* __restrict__ place, const float* __restrict__ other,
    const float* __restrict__ doc,  const float* __restrict__ cemb,
    const float* __restrict__ Wt2c, const float* __restrict__ bt2c,
    const float* __restrict__ Wcode, const float* __restrict__ bcode,
    const float* __restrict__ Wctx, const float* __restrict__ bctx,
    const float* __restrict__ Wcet, const float* __restrict__ bcet,
    const float* __restrict__ codeTab,
    const int* __restrict__ fcodes, const int* __restrict__ ccodes,
    const float* __restrict__ gaz,
    int nb, int cb, int cnb, int B, int nCtry, int nCodes)
{
    __shared__ __align__(16) float sA[64 * SA_STR];   // 25.6KB
    __shared__ __align__(16) float sB[32 * SB_STR];   // 12.8KB
    __shared__ float sBias[32];

    const int bid = blockIdx.x;
    const int tid = threadIdx.x;
    const int warp = tid >> 5, lane = tid & 31;
    const int gid = lane >> 2, tig = lane & 3;
    const int totJobs = 3 * nb + cb;

    if (bid < totJobs) {
        int job, rb;
        if      (bid <     nb) { job = 0; rb = bid; }
        else if (bid < 2 * nb) { job = 1; rb = bid - nb; }
        else if (bid < 3 * nb) { job = 2; rb = bid - 2 * nb; }
        else                   { job = 3; rb = bid - 3 * nb; }
        const int rowbase = rb * 64;
        const int nRows = (job == 3) ? nCtry : B;
        const float* src = (job == 0) ? place : (job == 1) ? other
                         : (job == 2) ? doc   : cemb;

        if (tid < 32) {
            float bv;
            if      (job == 0) bv = (tid < 24) ? bt2c[tid] : bcode[tid - 24];
            else if (job == 3) bv = (tid < 24) ? bcet[tid] : 0.f;
            else               bv = (tid < 24) ? bctx[tid] : 0.f;
            sBias[tid] = bv;
        }

        float c[4][4];
        #pragma unroll
        for (int i = 0; i < 4; i++)
            #pragma unroll
            for (int j = 0; j < 4; j++) c[i][j] = 0.f;

        #pragma unroll 1
        for (int ch = 0; ch < NCHUNK; ch++) {
            const int k0 = ch * KC;
            __syncthreads();
            // ---- stage A: 64 rows x 96 cols = 1536 float4, 12/thread ----
            #pragma unroll
            for (int i = 0; i < 12; i++) {
                int idx = tid + i * 128;
                int r = idx / 24, c4 = idx - r * 24;
                int gr = min(rowbase + r, nRows - 1);
                float4 v = __ldg((const float4*)(src + (size_t)gr * BERT + k0 + c4 * 4));
                float* d = sA + r * SA_STR + c4 * 4;
                d[0] = to_tf32(v.x); d[1] = to_tf32(v.y);
                d[2] = to_tf32(v.z); d[3] = to_tf32(v.w);
            }
            // ---- stage B transposed: sB[n][k], 32 x 96 = 768 float4, 6/thread ----
            #pragma unroll
            for (int i = 0; i < 6; i++) {
                int idx = tid + i * 128;
                int n = idx / 24, c4 = idx - n * 24;
                const float* wr;
                if      (job == 0) wr = (n < 24) ? Wt2c + n * BERT
                                                 : Wcode + (n - 24) * BERT;
                else if (job == 3) wr = Wcet + min(n, 23) * BERT;
                else               wr = Wctx + min(n, 23) * BERT;
                float4 v = __ldg((const float4*)(wr + k0 + c4 * 4));
                float* d = sB + n * SB_STR + c4 * 4;
                d[0] = to_tf32(v.x); d[1] = to_tf32(v.y);
                d[2] = to_tf32(v.z); d[3] = to_tf32(v.w);
            }
            __syncthreads();
            // ---- compute: 12 k-steps x 4 n-tiles ----
            const float* pa = sA + (warp * 16 + gid) * SA_STR + tig;
            #pragma unroll
            for (int kk = 0; kk < 12; kk++) {
                int kb = kk * 8;
                float a0 = pa[kb];
                float a1 = pa[8 * SA_STR + kb];
                float a2 = pa[kb + 4];
                float a3 = pa[8 * SA_STR + kb + 4];
                #pragma unroll
                for (int nt = 0; nt < 4; nt++) {
                    const float* pb = sB + (nt * 8 + gid) * SB_STR + kb + tig;
                    float b0 = pb[0];
                    float b1 = pb[4];
                    mma_tf32(c[nt], a0, a1, a2, a3, b0, b1);
                }
            }
        }

        // ---- store (C frag: rows gid/gid+8, cols 2tig,2tig+1 per n-tile) ----
        const int r0 = rowbase + warp * 16 + gid;
        const int r1 = r0 + 8;
        if (job < 3) {
            const int colbase = (job == 0) ? 0 : (job == 1) ? 32 : 56;
            const int ntMax = (job == 0) ? 4 : 3;
            #pragma unroll
            for (int nt = 0; nt < 4; nt++) {
                if (nt >= ntMax) break;
                int n0 = nt * 8 + 2 * tig;
                float b0 = sBias[n0], b1 = sBias[n0 + 1];
                if (r0 < B) {
                    float2 v = make_float2(c[nt][0] + b0, c[nt][1] + b1);
                    *(float2*)&g_proj[r0 * 80 + colbase + n0] = v;
                }
                if (r1 < B) {
                    float2 v = make_float2(c[nt][2] + b0, c[nt][3] + b1);
                    *(float2*)&g_proj[r1 * 80 + colbase + n0] = v;
                }
            }
        } else {
            // cet: store raw values + bias, then in-register norms
            float s0 = 0.f, s1 = 0.f;
            #pragma unroll
            for (int nt = 0; nt < 3; nt++) {
                int n0 = nt * 8 + 2 * tig;
                float b0 = sBias[n0], b1 = sBias[n0 + 1];
                float v00 = c[nt][0] + b0, v01 = c[nt][1] + b1;
                float v10 = c[nt][2] + b0, v11 = c[nt][3] + b1;
                if (r0 < nCtry) {
                    float2 v = make_float2(v00, v01);
                    *(float2*)&g_cet[r0 * CTRY + n0] = v;
                }
                if (r1 < nCtry) {
                    float2 v = make_float2(v10, v11);
                    *(float2*)&g_cet[r1 * CTRY + n0] = v;
                }
                s0 += v00 * v00 + v01 * v01;
                s1 += v10 * v10 + v11 * v11;
            }
            s0 += __shfl_xor_sync(0xffffffffu, s0, 1);
            s0 += __shfl_xor_sync(0xffffffffu, s0, 2);
            s1 += __shfl_xor_sync(0xffffffffu, s1, 1);
            s1 += __shfl_xor_sync(0xffffffffu, s1, 2);
            if (tig == 0) {
                if (r0 < nCtry) g_cetn[r0] = sqrtf(s0);
                if (r1 < nCtry) g_cetn[r1] = sqrtf(s1);
            }
        }
    } else if (bid < totJobs + cnb) {
        // ---------- code-embedding norms ----------
        int i = (bid - totJobs) * 128 + tid;
        if (i < nCodes) {
            float s = 0.f;
            #pragma unroll
            for (int j = 0; j < CODE; j++) { float v = codeTab[i * CODE + j]; s += v * v; }
            g_coden[i] = sqrtf(s);
        }
    } else {
        // ---------- L2 prefetch of k_mlp inputs ----------
        const int PFT = PF_BLK * 128;
        int t = (bid - totJobs - cnb) * 128 + tid;
        int gl = (B * CMAX * GAZ * 4 + 127) >> 7;
        for (int j = t; j < gl; j += PFT)
            pf_l2((const char*)gaz + ((size_t)j << 7));
        int cl = (B * CMAX * 4 + 127) >> 7;
        for (int j = t; j < cl; j += PFT) {
            pf_l2((const char*)fcodes + ((size_t)j << 7));
            pf_l2((const char*)ccodes + ((size_t)j << 7));
        }
    }
}

// =====================================================================
// k_mlp — VERBATIM the R7-measured 19.07us version.
// 128 thr = 4 rows x 32 lanes; each lane does candidates c, c+32.
// =====================================================================
__global__ void __launch_bounds__(128, 5) k_mlp(
    const int* __restrict__ fcodes, const int* __restrict__ ccodes,
    const float* __restrict__ gaz,  const float* __restrict__ codeTab,
    const float* __restrict__ W1, const float* __restrict__ b1,
    const float* __restrict__ W2, const float* __restrict__ b2,
    const float* __restrict__ WL, const float* __restrict__ bL,
    float* __restrict__ out, int Bn)
{
    __shared__ __align__(16) float sW1T[NFEAT * MIX];   // [q][j]
    __shared__ __align__(16) float sW2[MIX * MIX];      // [j][q]
    __shared__ __align__(16) float sB1[MIX];
    __shared__ float sB2[MIX], sWL[MIX];
    __shared__ __align__(16) float sGaz[4 * CMAX * GAZ];
    __shared__ __align__(16) float sX[4 * 80];
    __shared__ float sN[4][4];
    __shared__ float sbL;

    const int tid = threadIdx.x;
    const int b0  = blockIdx.x * 4;

    for (int i = tid; i < NFEAT * MIX; i += 128) {
        int q = i / MIX, j = i - q * MIX;
        sW1T[i] = W1[j * NFEAT + q];
    }
    for (int i = tid; i < MIX * MIX; i += 128) sW2[i] = W2[i];
    if (tid < MIX) { sB1[tid] = b1[tid]; sB2[tid] = b2[tid]; sWL[tid] = WL[tid]; }
    if (tid == 0) sbL = bL[0];
    {
        int cnt = min(576, (Bn - b0) * 144);
        const float4* gp = (const float4*)gaz + (size_t)b0 * 144;
        float4* sp = (float4*)sGaz;
        for (int i = tid; i < cnt; i += 128) sp[i] = __ldg(gp + i);
    }
    for (int i = tid; i < 4 * 80; i += 128) {
        int bb = min(b0 + i / 80, Bn - 1);
        sX[i] = g_proj[bb * 80 + (i % 80)];
    }
    __syncthreads();

    if (tid < 16) {
        int gg = tid >> 2, which = tid & 3;
        int off = (which == 0) ? 0 : (which == 1) ? 24 : (which == 2) ? 32 : 56;
        int cnt = (which == 1) ? CODE : CTRY;
        float ss = 0.f;
        for (int j = 0; j < cnt; j++) { float v = sX[gg * 80 + off + j]; ss += v * v; }
        sN[gg][which] = fmaxf(sqrtf(ss), 1e-8f);
    }
    __syncthreads();

    const int g    = tid >> 5;
    const int lane = tid & 31;
    const int b    = min(b0 + g, Bn - 1);
    const int idx0 = b * CMAX + lane;
    const int idx1 = idx0 + 32;
    const int fc0 = fcodes[idx0], cc0 = ccodes[idx0];
    const int fc1 = fcodes[idx1], cc1 = ccodes[idx1];
    const float* sx = sX + g * 80;

    const ulonglong2* cet0 = (const ulonglong2*)(g_cet + cc0 * CTRY);
    const ulonglong2* cet1 = (const ulonglong2*)(g_cet + cc1 * CTRY);
    const u64* x1 = (const u64*)(sx);
    const u64* x3 = (const u64*)(sx + 32);
    const u64* x4 = (const u64*)(sx + 56);
    u64 p10=0, p30=0, p40=0, p11=0, p31=0, p41=0;
    #pragma unroll
    for (int j = 0; j < 6; j++) {
        ulonglong2 c0 = __ldg(cet0 + j);
        ulonglong2 c1 = __ldg(cet1 + j);
        u64 xa = x1[2*j], xb = x1[2*j+1];
        ffma2(p10, xa, c0.x); ffma2(p10, xb, c0.y);
        ffma2(p11, xa, c1.x); ffma2(p11, xb, c1.y);
        xa = x3[2*j]; xb = x3[2*j+1];
        ffma2(p30, xa, c0.x); ffma2(p30, xb, c0.y);
        ffma2(p31, xa, c1.x); ffma2(p31, xb, c1.y);
        xa = x4[2*j]; xb = x4[2*j+1];
        ffma2(p40, xa, c0.x); ffma2(p40, xb, c0.y);
        ffma2(p41, xa, c1.x); ffma2(p41, xb, c1.y);
    }
    const ulonglong2* fe0 = (const ulonglong2*)(codeTab + fc0 * CODE);
    const ulonglong2* fe1 = (const ulonglong2*)(codeTab + fc1 * CODE);
    const u64* x2p = (const u64*)(sx + 24);
    u64 p20 = 0, p21 = 0;
    #pragma unroll
    for (int j = 0; j < 2; j++) {
        ulonglong2 c0 = __ldg(fe0 + j);
        ulonglong2 c1 = __ldg(fe1 + j);
        u64 xa = x2p[2*j], xb = x2p[2*j+1];
        ffma2(p20, xa, c0.x); ffma2(p20, xb, c0.y);
        ffma2(p21, xa, c1.x); ffma2(p21, xb, c1.y);
    }
    float nb0 = fmaxf(g_cetn[cc0], 1e-8f);
    float nb1 = fmaxf(g_cetn[cc1], 1e-8f);
    float feat0[4], feat1[4];
    feat0[0] = __fdividef(hsum2(p10), sN[g][0] * nb0);
    feat0[1] = __fdividef(hsum2(p20), sN[g][1] * fmaxf(g_coden[fc0], 1e-8f));
    feat0[2] = __fdividef(hsum2(p30), sN[g][2] * nb0);
    feat0[3] = __fdividef(hsum2(p40), sN[g][3] * nb0);
    feat1[0] = __fdividef(hsum2(p11), sN[g][0] * nb1);
    feat1[1] = __fdividef(hsum2(p21), sN[g][1] * fmaxf(g_coden[fc1], 1e-8f));
    feat1[2] = __fdividef(hsum2(p31), sN[g][2] * nb1);
    feat1[3] = __fdividef(hsum2(p41), sN[g][3] * nb1);

    u64 a0[12], a1[12];
    const u64* b1p = (const u64*)sB1;
    #pragma unroll
    for (int j = 0; j < 12; j++) { a0[j] = b1p[j]; a1[j] = b1p[j]; }

    const float* gz0 = sGaz + ((g * CMAX) + lane) * GAZ;
    const float* gz1 = gz0 + 32 * GAZ;
    #pragma unroll
    for (int q = 0; q < NFEAT; q++) {
        float f0 = (q < 4) ? feat0[q] : gz0[q - 4];
        float f1 = (q < 4) ? feat1[q] : gz1[q - 4];
        u64 ff0 = pack2(f0, f0), ff1 = pack2(f1, f1);
        const ulonglong2* wc = (const ulonglong2*)(sW1T + q * MIX);
        #pragma unroll
        for (int j2 = 0; j2 < 6; j2++) {
            ulonglong2 wv = wc[j2];
            ffma2(a0[2*j2],   ff0, wv.x); ffma2(a0[2*j2+1], ff0, wv.y);
            ffma2(a1[2*j2],   ff1, wv.x); ffma2(a1[2*j2+1], ff1, wv.y);
        }
    }
    #pragma unroll
    for (int j = 0; j < 12; j++) {
        float lo, hi;
        unpack2(a0[j], lo, hi); a0[j] = pack2(sigf(lo), sigf(hi));
        unpack2(a1[j], lo, hi); a1[j] = pack2(sigf(lo), sigf(hi));
    }

    float last0 = sbL, last1 = sbL;
    #pragma unroll
    for (int j = 0; j < MIX; j++) {
        const ulonglong2* wr = (const ulonglong2*)(sW2 + j * MIX);
        u64 s0 = 0ull, s1 = 0ull;
        #pragma unroll
        for (int q2 = 0; q2 < 6; q2++) {
            ulonglong2 wv = wr[q2];
            ffma2(s0, a0[2*q2],   wv.x); ffma2(s0, a0[2*q2+1], wv.y);
            ffma2(s1, a1[2*q2],   wv.x); ffma2(s1, a1[2*q2+1], wv.y);
        }
        float v0 = sB2[j] + hsum2(s0);
        float v1 = sB2[j] + hsum2(s1);
        last0 = fmaf(sWL[j], sigf(v0), last0);
        last1 = fmaf(sWL[j], sigf(v1), last1);
    }

    float m = fmaxf(last0, last1);
    #pragma unroll
    for (int o = 16; o; o >>= 1) m = fmaxf(m, __shfl_xor_sync(0xffffffffu, m, o));
    float e0 = __expf(last0 - m);
    float e1 = __expf(last1 - m);
    float ss = e0 + e1;
    #pragma unroll
    for (int o = 16; o; o >>= 1) ss += __shfl_xor_sync(0xffffffffu, ss, o);
    float inv = __fdividef(1.f, ss);
    if (b0 + g < Bn) {
        out[idx0] = e0 * inv;
        out[idx1] = e1 * inv;
    }
}

// =====================================================================
extern "C" void kernel_launch(void* const* d_in, const int* in_sizes, int n_in,
                              void* d_out, int out_size)
{
    const float* place  = (const float*)d_in[0];
    const float* other  = (const float*)d_in[1];
    const float* doc    = (const float*)d_in[2];
    const int*   fcodes = (const int*)  d_in[3];
    const int*   ccodes = (const int*)  d_in[4];
    const float* gaz    = (const float*)d_in[5];
    const float* codeTab= (const float*)d_in[6];
    const float* ctryTab= (const float*)d_in[7];
    const float* Wcet   = (const float*)d_in[8];
    const float* bcet   = (const float*)d_in[9];
    const float* Wt2c   = (const float*)d_in[10];
    const float* bt2c   = (const float*)d_in[11];
    const float* Wctx   = (const float*)d_in[12];
    const float* bctx   = (const float*)d_in[13];
    const float* Wcode  = (const float*)d_in[14];
    const float* bcode  = (const float*)d_in[15];
    const float* W1     = (const float*)d_in[16];
    const float* b1     = (const float*)d_in[17];
    const float* W2     = (const float*)d_in[18];
    const float* b2     = (const float*)d_in[19];
    const float* WL     = (const float*)d_in[20];
    const float* bL     = (const float*)d_in[21];
    float* out = (float*)d_out;

    int B      = in_sizes[0] / BERT;
    int nCtry  = in_sizes[7] / BERT;
    int nCodes = in_sizes[6] / CODE;

    int nb  = (B + 63) / 64;          // 32 blocks per batch-GEMM job
    int cb  = (nCtry + 63) / 64;      // cet job blocks
    int cnb = (nCodes + 127) / 128;   // code-norm blocks
    int grid = 3 * nb + cb + cnb + PF_BLK;

    k_mma<<<grid, 128>>>(place, other, doc, ctryTab,
                         Wt2c, bt2c, Wcode, bcode, Wctx, bctx,
                         Wcet, bcet, codeTab, fcodes, ccodes, gaz,
                         nb, cb, cnb, B, nCtry, nCodes);
    k_mlp<<<(B + 3) / 4, 128>>>(fcodes, ccodes, gaz, codeTab,
                                W1, b1, W2, b2, WL, bL, out, B);
}